// round 14
// baseline (speedup 1.0000x reference)
#include <cuda_runtime.h>
#include <cstdint>

// ---------------- constants ----------------
#define B_   16
#define N_   4096
#define M_   77
#define QDIM 1024
#define CDIM 768
#define H_   8
#define D_   64
#define INNER (H_*D_)   // 512

// ---------------- scratch (device globals: allocation-free) ----------------
__device__ float g_xr[(long)B_*N_*QDIM];    // tf32-rounded x
__device__ float g_cr[(long)B_*M_*CDIM];    // tf32-rounded ctx
__device__ float g_wq[QDIM*INNER];          // tf32-rounded weights (original layout)
__device__ float g_wk[CDIM*INNER];
__device__ float g_wv[CDIM*INNER];
__device__ float g_wo[INNER*QDIM];
__device__ float g_q[(long)B_*N_*INNER];
__device__ float g_k[(long)B_*M_*INNER];
__device__ float g_v[(long)B_*M_*INNER];
__device__ float g_a[(long)B_*N_*INNER];    // tf32-rounded by attn

// ---------------- helpers ----------------
__device__ __forceinline__ float tf32r(float x) {
    uint32_t u;
    asm("cvt.rna.tf32.f32 %0, %1;" : "=r"(u) : "f"(x));
    return __uint_as_float(u);
}

__device__ __forceinline__ void cp16(void* smem_dst, const void* gmem_src, bool pred) {
    uint32_t s = (uint32_t)__cvta_generic_to_shared(smem_dst);
    int sz = pred ? 16 : 0;
    asm volatile("cp.async.cg.shared.global [%0], [%1], 16, %2;\n"
                 :: "r"(s), "l"(gmem_src), "r"(sz));
}
__device__ __forceinline__ void cp_commit() {
    asm volatile("cp.async.commit_group;\n" ::: "memory");
}
__device__ __forceinline__ void cp_wait2() {
    asm volatile("cp.async.wait_group 2;\n" ::: "memory");
}

__device__ __forceinline__ void mma_tf32(float c[4], const uint32_t a[4], const uint32_t b[2]) {
    asm volatile(
        "mma.sync.aligned.m16n8k8.row.col.f32.tf32.tf32.f32 "
        "{%0,%1,%2,%3}, {%4,%5,%6,%7}, {%8,%9}, {%0,%1,%2,%3};\n"
        : "+f"(c[0]), "+f"(c[1]), "+f"(c[2]), "+f"(c[3])
        : "r"(a[0]), "r"(a[1]), "r"(a[2]), "r"(a[3]), "r"(b[0]), "r"(b[1]));
}

// ---------------- tf32 rounding pass (vectorized) ----------------
__global__ __launch_bounds__(256) void tf32_round(const float4* __restrict__ in,
                                                  float4* __restrict__ out, int n4) {
    int i = blockIdx.x * 256 + threadIdx.x;
    if (i < n4) {
        float4 v = in[i];
        v.x = tf32r(v.x); v.y = tf32r(v.y); v.z = tf32r(v.z); v.w = tf32r(v.w);
        out[i] = v;
    }
}

// ---------------- tf32 tensor-core GEMM: C = A(MxK) @ B(KxN) [+bias] ----------------
// BM=128, BN=128, BK=32; 256 threads = 8 warps (4 M x 2 N), warp tile 32x64.
// 3-stage cp.async pipeline. A,B pre-rounded tf32. N%128==0, K%32==0; M ragged OK.
#define GBM 128
#define GBN 128
#define GBK 32
#define STAGES 3
#define ASTRIDE (GBK + 4)    // 36 floats: A frag bank = (4g+t4)%32, conflict-free
#define BSTRIDE (GBN + 8)    // 136 floats: B frag bank = (8t4+cc)%32, conflict-free
#define A_FLOATS (GBM * ASTRIDE)             // 4608
#define B_FLOATS (GBK * BSTRIDE)             // 4352
#define SMEM_FLOATS (STAGES * (A_FLOATS + B_FLOATS))
#define SMEM_BYTES  (SMEM_FLOATS * 4)        // 107520

__global__ __launch_bounds__(256, 1) void sgemm_tf32(
    int M, int N, int K,
    const float* __restrict__ A, const float* __restrict__ Bm,
    const float* __restrict__ bias, float* __restrict__ C)
{
    extern __shared__ float sm[];
    float* Asm = sm;                         // [STAGES][GBM][ASTRIDE]
    float* Bsm = sm + STAGES * A_FLOATS;     // [STAGES][GBK][BSTRIDE]

    const int tid  = threadIdx.x;
    const int lane = tid & 31;
    const int wid  = tid >> 5;
    const int warpRow = (wid & 3) * 32;   // 0,32,64,96
    const int warpCol = (wid >> 2) * 64;  // 0,64
    const int g  = lane >> 2;             // 0..7
    const int t4 = lane & 3;              // 0..3

    const int rowBase = blockIdx.y * GBM;
    const int colBase = blockIdx.x * GBN;

    float c[2][8][4];
    #pragma unroll
    for (int mi = 0; mi < 2; mi++)
        #pragma unroll
        for (int ni = 0; ni < 8; ni++)
            #pragma unroll
            for (int r = 0; r < 4; r++) c[mi][ni][r] = 0.f;

    const int T = K / GBK;

    // ---- stage load: A tile 128x32 (1024 float4), B tile 32x128 (1024 float4) ----
    auto load_tile = [&](int t) {
        const int stg = t % STAGES;
        const int k0  = t * GBK;
        float* As = Asm + stg * A_FLOATS;
        float* Bs = Bsm + stg * B_FLOATS;
        #pragma unroll
        for (int i = 0; i < 4; i++) {
            int chunk = tid + i * 256;         // 0..1023
            int row = chunk >> 3;              // 0..127
            int c16 = (chunk & 7) << 2;        // 0,4,...,28
            int gr = rowBase + row;
            bool p = gr < M;
            cp16(&As[row * ASTRIDE + c16],
                 A + (long)(p ? gr : 0) * K + k0 + c16, p);
        }
        #pragma unroll
        for (int i = 0; i < 4; i++) {
            int chunk = tid + i * 256;         // 0..1023
            int kr  = chunk >> 5;              // 0..31
            int c16 = (chunk & 31) << 2;       // 0..124
            cp16(&Bs[kr * BSTRIDE + c16],
                 Bm + (long)(k0 + kr) * N + colBase + c16, true);
        }
        cp_commit();
    };

    // prologue: fill the pipeline (T >= STAGES for all call sites)
    load_tile(0); load_tile(1); load_tile(2);

    for (int t = 0; t < T; t++) {
        cp_wait2();           // <=2 groups pending -> tile t complete
        __syncthreads();

        const int stg = t % STAGES;
        const float* As = Asm + stg * A_FLOATS;
        const float* Bs = Bsm + stg * B_FLOATS;

        #pragma unroll
        for (int kk = 0; kk < 4; kk++) {
            const int k0 = kk * 8;
            uint32_t a[2][4];
            #pragma unroll
            for (int mi = 0; mi < 2; mi++) {
                int r = warpRow + mi * 16;
                a[mi][0] = __float_as_uint(As[(r + g    ) * ASTRIDE + k0 + t4    ]);
                a[mi][1] = __float_as_uint(As[(r + g + 8) * ASTRIDE + k0 + t4    ]);
                a[mi][2] = __float_as_uint(As[(r + g    ) * ASTRIDE + k0 + t4 + 4]);
                a[mi][3] = __float_as_uint(As[(r + g + 8) * ASTRIDE + k0 + t4 + 4]);
            }
            uint32_t b[8][2];
            #pragma unroll
            for (int ni = 0; ni < 8; ni++) {
                int cc = warpCol + ni * 8 + g;
                b[ni][0] = __float_as_uint(Bs[(k0 + t4    ) * BSTRIDE + cc]);
                b[ni][1] = __float_as_uint(Bs[(k0 + t4 + 4) * BSTRIDE + cc]);
            }
            #pragma unroll
            for (int mi = 0; mi < 2; mi++)
                #pragma unroll
                for (int ni = 0; ni < 8; ni++)
                    mma_tf32(c[mi][ni], a[mi], b[ni]);
        }
        __syncthreads();      // all warps done reading stage stg
        if (t + STAGES < T) load_tile(t + STAGES);
    }

    // ---- epilogue ----
    #pragma unroll
    for (int ni = 0; ni < 8; ni++) {
        int col = colBase + warpCol + ni * 8 + t4 * 2;
        float b0 = 0.f, b1 = 0.f;
        if (bias) { b0 = bias[col]; b1 = bias[col + 1]; }
        #pragma unroll
        for (int mi = 0; mi < 2; mi++) {
            int row0 = rowBase + warpRow + mi * 16 + g;
            int row1 = row0 + 8;
            if (row0 < M) {
                float2 o; o.x = c[mi][ni][0] + b0; o.y = c[mi][ni][1] + b1;
                *reinterpret_cast<float2*>(&C[(long)row0 * N + col]) = o;
            }
            if (row1 < M) {
                float2 o; o.x = c[mi][ni][2] + b0; o.y = c[mi][ni][3] + b1;
                *reinterpret_cast<float2*>(&C[(long)row1 * N + col]) = o;
            }
        }
    }
}

// ---------------- fused flash-style attention (lane-pair per query row) ----------------
// grid = (N/128, H, B), 256 threads; lane pair (2k,2k+1) handles one row, 32 dims each.
__global__ __launch_bounds__(256) void attn_kernel(
    const float* __restrict__ q, const float* __restrict__ kbuf,
    const float* __restrict__ vbuf, float* __restrict__ out)
{
    __shared__ float Ks[M_][D_];
    __shared__ float Vs[M_][D_];

    const int b = blockIdx.z, h = blockIdx.y;
    const int tid = threadIdx.x;
    const int rowIb = tid >> 1;
    const int half  = tid & 1;
    const int n = blockIdx.x * 128 + rowIb;
    const int dbase = half * 32;
    const float scale = 0.125f;  // 1/sqrt(64)

    const long kvbase = ((long)b * M_) * INNER + h * D_;
    for (int idx = tid; idx < M_ * (D_ / 4); idx += 256) {
        int m  = idx >> 4;
        int d4 = (idx & 15) << 2;
        *reinterpret_cast<float4*>(&Ks[m][d4]) =
            *reinterpret_cast<const float4*>(&kbuf[kvbase + (long)m * INNER + d4]);
        *reinterpret_cast<float4*>(&Vs[m][d4]) =
            *reinterpret_cast<const float4*>(&vbuf[kvbase + (long)m * INNER + d4]);
    }
    __syncthreads();

    float qr[32];
    const long qbase = ((long)b * N_ + n) * INNER + h * D_;
    #pragma unroll
    for (int d4 = 0; d4 < 32; d4 += 4) {
        float4 t = *reinterpret_cast<const float4*>(&q[qbase + dbase + d4]);
        qr[d4 + 0] = t.x * scale; qr[d4 + 1] = t.y * scale;
        qr[d4 + 2] = t.z * scale; qr[d4 + 3] = t.w * scale;
    }

    float acc[32];
    #pragma unroll
    for (int d = 0; d < 32; d++) acc[d] = 0.f;
    float mrun = -1e30f, srun = 0.f;

    for (int m = 0; m < M_; m++) {
        float sp = 0.f;
        #pragma unroll
        for (int d = 0; d < 32; d++) sp += qr[d] * Ks[m][dbase + d];
        float s = sp + __shfl_xor_sync(0xffffffffu, sp, 1);
        if (s <= mrun) {
            float p = __expf(s - mrun);
            srun += p;
            #pragma unroll
            for (int d = 0; d < 32; d++) acc[d] += p * Vs[m][dbase + d];
        } else {
            float corr = __expf(mrun - s);
            mrun = s;
            srun = srun * corr + 1.f;
            #pragma unroll
            for (int d = 0; d < 32; d++) acc[d] = acc[d] * corr + Vs[m][dbase + d];
        }
    }

    const float inv = 1.f / srun;
    #pragma unroll
    for (int d4 = 0; d4 < 32; d4 += 4) {
        float4 o;
        o.x = tf32r(acc[d4 + 0] * inv); o.y = tf32r(acc[d4 + 1] * inv);
        o.z = tf32r(acc[d4 + 2] * inv); o.w = tf32r(acc[d4 + 3] * inv);
        *reinterpret_cast<float4*>(&out[qbase + dbase + d4]) = o;
    }
}

// ---------------- launch ----------------
extern "C" void kernel_launch(void* const* d_in, const int* in_sizes, int n_in,
                              void* d_out, int out_size)
{
    const float* x   = (const float*)d_in[0];
    const float* ctx = (const float*)d_in[1];
    const float* Wq  = (const float*)d_in[2];
    const float* Wk  = (const float*)d_in[3];
    const float* Wv  = (const float*)d_in[4];
    const float* Wo  = (const float*)d_in[5];
    const float* bo  = (const float*)d_in[6];
    float* out = (float*)d_out;

    float *xr, *cr, *wq, *wk, *wv, *wo, *qb, *kb, *vb, *ab;
    cudaGetSymbolAddress((void**)&xr, g_xr);
    cudaGetSymbolAddress((void**)&cr, g_cr);
    cudaGetSymbolAddress((void**)&wq, g_wq);
    cudaGetSymbolAddress((void**)&wk, g_wk);
    cudaGetSymbolAddress((void**)&wv, g_wv);
    cudaGetSymbolAddress((void**)&wo, g_wo);
    cudaGetSymbolAddress((void**)&qb, g_q);
    cudaGetSymbolAddress((void**)&kb, g_k);
    cudaGetSymbolAddress((void**)&vb, g_v);
    cudaGetSymbolAddress((void**)&ab, g_a);

    cudaFuncSetAttribute(sgemm_tf32, cudaFuncAttributeMaxDynamicSharedMemorySize, SMEM_BYTES);

    auto roundit = [](const float* src, float* dst, long n) {
        int n4 = (int)(n / 4);
        tf32_round<<<(n4 + 255) / 256, 256>>>((const float4*)src, (float4*)dst, n4);
    };

    // Pre-round all GEMM operands to tf32 (RNA) so GEMMs can feed mma raw.
    roundit(x,   xr, (long)B_ * N_ * QDIM);
    roundit(ctx, cr, (long)B_ * M_ * CDIM);
    roundit(Wq,  wq, (long)QDIM * INNER);
    roundit(Wk,  wk, (long)CDIM * INNER);
    roundit(Wv,  wv, (long)CDIM * INNER);
    roundit(Wo,  wo, (long)INNER * QDIM);

    const int MKV = B_ * M_;  // 1232 (ragged)

    // k = ctx @ Wk, v = ctx @ Wv   (1232 x 512, K=768)
    sgemm_tf32<<<dim3(INNER / GBN, (MKV + GBM - 1) / GBM), 256, SMEM_BYTES>>>(
        MKV, INNER, CDIM, cr, wk, nullptr, kb);
    sgemm_tf32<<<dim3(INNER / GBN, (MKV + GBM - 1) / GBM), 256, SMEM_BYTES>>>(
        MKV, INNER, CDIM, cr, wv, nullptr, vb);

    // q = x @ Wq   (65536 x 512, K=1024)
    sgemm_tf32<<<dim3(INNER / GBN, (B_ * N_) / GBM), 256, SMEM_BYTES>>>(
        B_ * N_, INNER, QDIM, xr, wq, nullptr, qb);

    // attention (emits tf32-rounded activations)
    attn_kernel<<<dim3(N_ / 128, H_, B_), 256>>>(qb, kb, vb, ab);

    // out = attn @ Wo + bo   (65536 x 1024, K=512)
    sgemm_tf32<<<dim3(QDIM / GBN, (B_ * N_) / GBM), 256, SMEM_BYTES>>>(
        B_ * N_, QDIM, INNER, ab, wo, bo, out);
}

// round 15
// speedup vs baseline: 1.0925x; 1.0925x over previous
#include <cuda_runtime.h>
#include <cstdint>

// ---------------- constants ----------------
#define B_   16
#define N_   4096
#define M_   77
#define QDIM 1024
#define CDIM 768
#define H_   8
#define D_   64
#define INNER (H_*D_)   // 512

// ---------------- scratch (device globals: allocation-free) ----------------
__device__ float g_xr[(long)B_*N_*QDIM];    // tf32-rounded x
__device__ float g_cr[(long)B_*M_*CDIM];    // tf32-rounded ctx
__device__ float g_wqt[(long)INNER*QDIM];   // Wq^T (512 x 1024), tf32, K-major
__device__ float g_wkt[(long)INNER*CDIM];   // Wk^T (512 x 768)
__device__ float g_wvt[(long)INNER*CDIM];   // Wv^T (512 x 768)
__device__ float g_wot[(long)QDIM*INNER];   // Wo^T (1024 x 512)
__device__ float g_q[(long)B_*N_*INNER];
__device__ float g_k[(long)B_*M_*INNER];
__device__ float g_v[(long)B_*M_*INNER];
__device__ float g_a[(long)B_*N_*INNER];    // tf32-rounded by attn

// ---------------- helpers ----------------
__device__ __forceinline__ float tf32r(float x) {
    uint32_t u;
    asm("cvt.rna.tf32.f32 %0, %1;" : "=r"(u) : "f"(x));
    return __uint_as_float(u);
}
__device__ __forceinline__ void cp16(void* smem_dst, const void* gmem_src, bool pred) {
    uint32_t s = (uint32_t)__cvta_generic_to_shared(smem_dst);
    int sz = pred ? 16 : 0;
    asm volatile("cp.async.cg.shared.global [%0], [%1], 16, %2;\n"
                 :: "r"(s), "l"(gmem_src), "r"(sz));
}
__device__ __forceinline__ void cp_commit() {
    asm volatile("cp.async.commit_group;\n" ::: "memory");
}
__device__ __forceinline__ void cp_wait0() {
    asm volatile("cp.async.wait_group 0;\n" ::: "memory");
}
__device__ __forceinline__ void mma_tf32(float c[4], const uint32_t a[4], const uint32_t b[2]) {
    asm volatile(
        "mma.sync.aligned.m16n8k8.row.col.f32.tf32.tf32.f32 "
        "{%0,%1,%2,%3}, {%4,%5,%6,%7}, {%8,%9}, {%0,%1,%2,%3};\n"
        : "+f"(c[0]), "+f"(c[1]), "+f"(c[2]), "+f"(c[3])
        : "r"(a[0]), "r"(a[1]), "r"(a[2]), "r"(a[3]), "r"(b[0]), "r"(b[1]));
}
__device__ __forceinline__ void ldsm4(uint32_t& r0, uint32_t& r1, uint32_t& r2, uint32_t& r3,
                                      uint32_t addr) {
    asm volatile("ldmatrix.sync.aligned.m8n8.x4.shared.b16 {%0,%1,%2,%3}, [%4];"
                 : "=r"(r0), "=r"(r1), "=r"(r2), "=r"(r3) : "r"(addr));
}

// ---------------- tf32 rounding pass ----------------
__global__ __launch_bounds__(256) void tf32_round(const float4* __restrict__ in,
                                                  float4* __restrict__ out, int n4) {
    int i = blockIdx.x * 256 + threadIdx.x;
    if (i < n4) {
        float4 v = in[i];
        v.x = tf32r(v.x); v.y = tf32r(v.y); v.z = tf32r(v.z); v.w = tf32r(v.w);
        out[i] = v;
    }
}

// ---------------- weight transpose (+tf32 round): WT[n][k] = r(W[k][n]) ----------------
__global__ __launch_bounds__(256) void transpose_tf32(const float* __restrict__ W,
                                                      float* __restrict__ WT, int K, int N) {
    __shared__ float t[32][33];
    const int kb = blockIdx.y * 32, nb = blockIdx.x * 32;
    const int tx = threadIdx.x, ty = threadIdx.y;  // (32, 8)
    #pragma unroll
    for (int i = 0; i < 32; i += 8)
        t[ty + i][tx] = W[(long)(kb + ty + i) * N + nb + tx];
    __syncthreads();
    #pragma unroll
    for (int i = 0; i < 32; i += 8)
        WT[(long)(nb + ty + i) * K + kb + tx] = tf32r(t[tx][ty + i]);
}

// ---------------- tf32 tensor GEMM: C(MxN) = A(MxK) @ BT(NxK)^T [+bias] ----------------
// BM=128, BN=128, BK=16; 128 threads = 4 warps (2x2), warp tile 64x64.
// Both operands K-major in smem (stride 20); ldmatrix.x4 fragment loads.
// 2-stage cp.async pipeline; M ragged OK; N%128==0, K%16==0.
#define GBM 128
#define GBN 128
#define GBK 16
#define ASTR 20                       // floats per smem row; ldmatrix banks 5j%8 distinct
#define STG_FLOATS (GBM * ASTR)       // 2560 floats per operand per stage
#define STG_BYTES  (STG_FLOATS * 4)   // 10240

__global__ __launch_bounds__(128) void sgemm_tf32(
    int M, int K,
    const float* __restrict__ A, const float* __restrict__ BT,
    const float* __restrict__ bias, float* __restrict__ C, int ldc)
{
    __shared__ float sAs[2][GBM][ASTR];
    __shared__ float sBs[2][GBM][ASTR];

    const int tid  = threadIdx.x;
    const int lane = tid & 31;
    const int wid  = tid >> 5;
    const int warpRow = (wid & 1) * 64;
    const int warpCol = (wid >> 1) * 64;
    const int g  = lane >> 2;
    const int t4 = lane & 3;

    const int rowBase = blockIdx.y * GBM;
    const int colBase = blockIdx.x * GBN;

    const uint32_t As_u = (uint32_t)__cvta_generic_to_shared(&sAs[0][0][0]);
    const uint32_t Bs_u = (uint32_t)__cvta_generic_to_shared(&sBs[0][0][0]);

    // ldmatrix per-lane offsets (floats)
    const int aRowOff = ((lane >> 3) & 1) * 8 + (lane & 7);
    const int aColOff = ((lane >> 4) & 1) * 4;
    const int bRowOff = ((lane >> 4) & 1) * 8 + (lane & 7);
    const int bColOff = ((lane >> 3) & 1) * 4;
    const uint32_t aBase = As_u + ((warpRow + aRowOff) * ASTR + aColOff) * 4;
    const uint32_t bBase = Bs_u + ((warpCol + bRowOff) * ASTR + bColOff) * 4;

    float c[4][8][4];
    #pragma unroll
    for (int mi = 0; mi < 4; mi++)
        #pragma unroll
        for (int ni = 0; ni < 8; ni++)
            #pragma unroll
            for (int r = 0; r < 4; r++) c[mi][ni][r] = 0.f;

    const int T = K / GBK;

    auto load_tile = [&](int t) {
        const int buf = t & 1;
        const int k0  = t * GBK;
        #pragma unroll
        for (int i = 0; i < 4; i++) {
            int chunk = tid + i * 128;          // 0..511
            int row = chunk >> 2;               // 0..127
            int c16 = (chunk & 3) << 2;         // 0,4,8,12
            int gr = rowBase + row;
            bool p = gr < M;
            cp16(&sAs[buf][row][c16], A + (long)(p ? gr : 0) * K + k0 + c16, p);
        }
        #pragma unroll
        for (int i = 0; i < 4; i++) {
            int chunk = tid + i * 128;
            int row = chunk >> 2;
            int c16 = (chunk & 3) << 2;
            cp16(&sBs[buf][row][c16], BT + (long)(colBase + row) * K + k0 + c16, true);
        }
        cp_commit();
    };

    load_tile(0);

    for (int t = 0; t < T; t++) {
        cp_wait0();
        __syncthreads();
        if (t + 1 < T) load_tile(t + 1);   // fills other buffer while we compute
        const int buf = t & 1;
        const uint32_t ab = aBase + buf * STG_BYTES;
        const uint32_t bb = bBase + buf * STG_BYTES;

        #pragma unroll
        for (int kk = 0; kk < 2; kk++) {
            const uint32_t koff = kk * 8 * 4;
            uint32_t a[4][4];
            #pragma unroll
            for (int mi = 0; mi < 4; mi++)
                ldsm4(a[mi][0], a[mi][1], a[mi][2], a[mi][3],
                      ab + mi * (16 * ASTR * 4) + koff);
            uint32_t b[8][2];
            #pragma unroll
            for (int p = 0; p < 4; p++)
                ldsm4(b[2 * p][0], b[2 * p][1], b[2 * p + 1][0], b[2 * p + 1][1],
                      bb + p * (16 * ASTR * 4) + koff);
            #pragma unroll
            for (int mi = 0; mi < 4; mi++)
                #pragma unroll
                for (int ni = 0; ni < 8; ni++)
                    mma_tf32(c[mi][ni], a[mi], b[ni]);
        }
        __syncthreads();
    }

    // ---- epilogue ----
    #pragma unroll
    for (int ni = 0; ni < 8; ni++) {
        int col = colBase + warpCol + ni * 8 + t4 * 2;
        float b0 = 0.f, b1 = 0.f;
        if (bias) { b0 = bias[col]; b1 = bias[col + 1]; }
        #pragma unroll
        for (int mi = 0; mi < 4; mi++) {
            int row0 = rowBase + warpRow + mi * 16 + g;
            int row1 = row0 + 8;
            if (row0 < M) {
                float2 o; o.x = c[mi][ni][0] + b0; o.y = c[mi][ni][1] + b1;
                *reinterpret_cast<float2*>(&C[(long)row0 * ldc + col]) = o;
            }
            if (row1 < M) {
                float2 o; o.x = c[mi][ni][2] + b0; o.y = c[mi][ni][3] + b1;
                *reinterpret_cast<float2*>(&C[(long)row1 * ldc + col]) = o;
            }
        }
    }
}

// ---------------- fused flash-style attention (lane-pair per query row) ----------------
__global__ __launch_bounds__(256) void attn_kernel(
    const float* __restrict__ q, const float* __restrict__ kbuf,
    const float* __restrict__ vbuf, float* __restrict__ out)
{
    __shared__ float Ks[M_][D_];
    __shared__ float Vs[M_][D_];

    const int b = blockIdx.z, h = blockIdx.y;
    const int tid = threadIdx.x;
    const int rowIb = tid >> 1;
    const int half  = tid & 1;
    const int n = blockIdx.x * 128 + rowIb;
    const int dbase = half * 32;
    const float scale = 0.125f;  // 1/sqrt(64)

    const long kvbase = ((long)b * M_) * INNER + h * D_;
    for (int idx = tid; idx < M_ * (D_ / 4); idx += 256) {
        int m  = idx >> 4;
        int d4 = (idx & 15) << 2;
        *reinterpret_cast<float4*>(&Ks[m][d4]) =
            *reinterpret_cast<const float4*>(&kbuf[kvbase + (long)m * INNER + d4]);
        *reinterpret_cast<float4*>(&Vs[m][d4]) =
            *reinterpret_cast<const float4*>(&vbuf[kvbase + (long)m * INNER + d4]);
    }
    __syncthreads();

    float qr[32];
    const long qbase = ((long)b * N_ + n) * INNER + h * D_;
    #pragma unroll
    for (int d4 = 0; d4 < 32; d4 += 4) {
        float4 t = *reinterpret_cast<const float4*>(&q[qbase + dbase + d4]);
        qr[d4 + 0] = t.x * scale; qr[d4 + 1] = t.y * scale;
        qr[d4 + 2] = t.z * scale; qr[d4 + 3] = t.w * scale;
    }

    float acc[32];
    #pragma unroll
    for (int d = 0; d < 32; d++) acc[d] = 0.f;
    float mrun = -1e30f, srun = 0.f;

    for (int m = 0; m < M_; m++) {
        float sp = 0.f;
        #pragma unroll
        for (int d = 0; d < 32; d++) sp += qr[d] * Ks[m][dbase + d];
        float s = sp + __shfl_xor_sync(0xffffffffu, sp, 1);
        if (s <= mrun) {
            float p = __expf(s - mrun);
            srun += p;
            #pragma unroll
            for (int d = 0; d < 32; d++) acc[d] += p * Vs[m][dbase + d];
        } else {
            float corr = __expf(mrun - s);
            mrun = s;
            srun = srun * corr + 1.f;
            #pragma unroll
            for (int d = 0; d < 32; d++) acc[d] = acc[d] * corr + Vs[m][dbase + d];
        }
    }

    const float inv = 1.f / srun;
    #pragma unroll
    for (int d4 = 0; d4 < 32; d4 += 4) {
        float4 o;
        o.x = tf32r(acc[d4 + 0] * inv); o.y = tf32r(acc[d4 + 1] * inv);
        o.z = tf32r(acc[d4 + 2] * inv); o.w = tf32r(acc[d4 + 3] * inv);
        *reinterpret_cast<float4*>(&out[qbase + dbase + d4]) = o;
    }
}

// ---------------- launch ----------------
extern "C" void kernel_launch(void* const* d_in, const int* in_sizes, int n_in,
                              void* d_out, int out_size)
{
    const float* x   = (const float*)d_in[0];
    const float* ctx = (const float*)d_in[1];
    const float* Wq  = (const float*)d_in[2];
    const float* Wk  = (const float*)d_in[3];
    const float* Wv  = (const float*)d_in[4];
    const float* Wo  = (const float*)d_in[5];
    const float* bo  = (const float*)d_in[6];
    float* out = (float*)d_out;

    float *xr, *cr, *wqt, *wkt, *wvt, *wot, *qb, *kb, *vb, *ab;
    cudaGetSymbolAddress((void**)&xr,  g_xr);
    cudaGetSymbolAddress((void**)&cr,  g_cr);
    cudaGetSymbolAddress((void**)&wqt, g_wqt);
    cudaGetSymbolAddress((void**)&wkt, g_wkt);
    cudaGetSymbolAddress((void**)&wvt, g_wvt);
    cudaGetSymbolAddress((void**)&wot, g_wot);
    cudaGetSymbolAddress((void**)&qb,  g_q);
    cudaGetSymbolAddress((void**)&kb,  g_k);
    cudaGetSymbolAddress((void**)&vb,  g_v);
    cudaGetSymbolAddress((void**)&ab,  g_a);

    auto roundit = [](const float* src, float* dst, long n) {
        int n4 = (int)(n / 4);
        tf32_round<<<(n4 + 255) / 256, 256>>>((const float4*)src, (float4*)dst, n4);
    };

    // Round activations; transpose+round weights to K-major.
    roundit(x,   xr, (long)B_ * N_ * QDIM);
    roundit(ctx, cr, (long)B_ * M_ * CDIM);
    transpose_tf32<<<dim3(INNER / 32, QDIM / 32), dim3(32, 8)>>>(Wq, wqt, QDIM, INNER);
    transpose_tf32<<<dim3(INNER / 32, CDIM / 32), dim3(32, 8)>>>(Wk, wkt, CDIM, INNER);
    transpose_tf32<<<dim3(INNER / 32, CDIM / 32), dim3(32, 8)>>>(Wv, wvt, CDIM, INNER);
    transpose_tf32<<<dim3(QDIM / 32, INNER / 32), dim3(32, 8)>>>(Wo, wot, INNER, QDIM);

    const int MKV = B_ * M_;  // 1232 (ragged)

    // k = ctx @ Wk, v = ctx @ Wv   (1232 x 512, K=768)
    sgemm_tf32<<<dim3(INNER / GBN, (MKV + GBM - 1) / GBM), 128>>>(
        MKV, CDIM, cr, wkt, nullptr, kb, INNER);
    sgemm_tf32<<<dim3(INNER / GBN, (MKV + GBM - 1) / GBM), 128>>>(
        MKV, CDIM, cr, wvt, nullptr, vb, INNER);

    // q = x @ Wq   (65536 x 512, K=1024)
    sgemm_tf32<<<dim3(INNER / GBN, (B_ * N_) / GBM), 128>>>(
        B_ * N_, QDIM, xr, wqt, nullptr, qb, INNER);

    // attention (emits tf32-rounded activations)
    attn_kernel<<<dim3(N_ / 128, H_, B_), 256>>>(qb, kb, vb, ab);

    // out = attn @ Wo + bo   (65536 x 1024, K=512)
    sgemm_tf32<<<dim3(QDIM / GBN, (B_ * N_) / GBM), 128>>>(
        B_ * N_, INNER, ab, wot, bo, out, QDIM);
}